// round 7
// baseline (speedup 1.0000x reference)
#include <cuda_runtime.h>
#include <mma.h>
#include <math.h>
#include <cstdint>

using namespace nvcuda;

#define NB   128
#define TPB  512
#define Bsz  128
#define Tsz  512
#define ISZ  128
#define Hsz  1024
#define ACCW 4096
#define SMEM_BYTES 141312   // (2*9216 A) + (2*8448 W) floats * 4B

// ---- preconverted weight planes: [k][n] per phase, tf32 hi/lo ----------------
#define WTOT 19005440
__device__ float g_whi[WTOT];
__device__ float g_wlo[WTOT];
#define OQ1(i) ((size_t)(i)*131072)
#define OR1(i) (393216 + (size_t)(i)*131072)
#define OL1    655360
#define OQ2(i) (5373952 + (size_t)(i)*1048576)
#define OR2(i) (8519680 + (size_t)(i)*1048576)
#define OL2    10616832

// ---------------- persistent state --------------------------------------------
__device__ float g_h1 [Bsz*Hsz];
__device__ float g_h1h[Bsz*Hsz];
__device__ float g_h1l[Bsz*Hsz];
__device__ float g_c1 [Bsz*Hsz];
__device__ float g_h2 [Bsz*Hsz];
__device__ float g_h2h[Bsz*Hsz];
__device__ float g_h2l[Bsz*Hsz];
__device__ float g_c2 [Bsz*Hsz];
__device__ float g_x  [Bsz*ISZ];
__device__ float g_xh [Bsz*ISZ];
__device__ float g_xl [Bsz*ISZ];
__device__ float g_x2 [Bsz*Hsz];
__device__ float g_x2h[Bsz*Hsz];
__device__ float g_x2l[Bsz*Hsz];
__device__ float g_hm [Bsz*Hsz];
__device__ float g_hmh[Bsz*Hsz];
__device__ float g_hml[Bsz*Hsz];
__device__ float g_acc[Bsz*ACCW];
__device__ int   g_cnt[64];
__device__ unsigned g_barcnt;
__device__ volatile unsigned g_bargen;

__device__ __forceinline__ float sigm(float z) { return 1.f / (1.f + expf(-z)); }
__device__ __forceinline__ float t32(float v)  { return wmma::__float_to_tf32(v); }

__device__ __forceinline__ void cpa16(unsigned int dst, const void* src) {
    asm volatile("cp.async.cg.shared.global [%0], [%1], 16;\n" :: "r"(dst), "l"(src));
}
__device__ __forceinline__ void cpa_commit() { asm volatile("cp.async.commit_group;\n"); }
__device__ __forceinline__ void cpa_waitall() { asm volatile("cp.async.wait_all;\n"); }

// ---------------- grid barrier ------------------------------------------------
__device__ __forceinline__ void gridbar() {
    __syncthreads();
    if (threadIdx.x == 0) {
        __threadfence();
        unsigned gen = g_bargen;
        if (atomicAdd(&g_barcnt, 1u) == (unsigned)(gridDim.x - 1)) {
            g_barcnt = 0;
            __threadfence();
            atomicExch((unsigned*)&g_bargen, gen + 1u);
        } else {
            while (g_bargen == gen) { __nanosleep(32); }
        }
        __threadfence();
    }
    __syncthreads();
}

// ---------------- weight preconversion (once per launch) ----------------------
__global__ void preconv_kernel(
    const float* c1Q, const float* c1R, const float* c1Wih, const float* c1Whh,
    const float* c2Q, const float* c2R, const float* c2Wih, const float* c2Whh)
{
    int seg = blockIdx.y;
    const float *src = 0, *src2 = 0;
    int K = 0, N = 0, LD = 0, K1 = 0, lstm = 0;
    size_t dst = 0;
    switch (seg) {
        case 0: case 1: case 2:
            src = c1Q + (size_t)seg*131072; K = 1024; N = 128; LD = 1024; dst = OQ1(seg); break;
        case 3: case 4:
            src = c1R + (size_t)(seg-3)*131072; K = 128; N = 1024; LD = 128; dst = OR1(seg-3); break;
        case 5:
            src = c1Wih; src2 = c1Whh; K = 1152; N = 4096; K1 = 128; lstm = 1; dst = OL1; break;
        case 6: case 7: case 8:
            src = c2Q + (size_t)(seg-6)*1048576; K = 1024; N = 1024; LD = 1024; dst = OQ2(seg-6); break;
        case 9: case 10:
            src = c2R + (size_t)(seg-9)*1048576; K = 1024; N = 1024; LD = 1024; dst = OR2(seg-9); break;
        default:
            src = c2Wih; src2 = c2Whh; K = 2048; N = 4096; K1 = 1024; lstm = 1; dst = OL2; break;
    }
    size_t tot = (size_t)K * N;
    for (size_t i = (size_t)blockIdx.x*blockDim.x + threadIdx.x; i < tot;
         i += (size_t)gridDim.x*blockDim.x) {
        int k = (int)(i / N), n = (int)(i % N);
        float v;
        if (!lstm) {
            v = src[(size_t)n*LD + k];
        } else {
            int g = n & 3, u = n >> 2;
            int row = g*Hsz + u;
            v = (k < K1) ? src[(size_t)row*K1 + k] : src2[(size_t)row*Hsz + (k - K1)];
        }
        float h = t32(v);
        g_whi[dst + i] = h;
        g_wlo[dst + i] = t32(v - h);
    }
}

// ---------------- phase descriptor --------------------------------------------
struct P {
    const float *A1h, *A1l, *A2h, *A2l; int K1, Ktot;  // A planes, k<K1->A1(stride K1) else A2(stride Hsz)
    size_t woff;
    int N, kch, lstm;
    const float *b1, *b2;
    const float *mult; int mstride;
    float *out, *outh, *outl; int ostride;
    float *fc, *fh, *fhh, *fhl;
};

// one GEMM phase: 128 x NSTRIP tile per CTA, split-K, 32-k macro-tiles,
// cp.async for BOTH pre-split A and W planes; 3xTF32 wmma, 2x2 warp frags.
template<int NSHIFT>
__device__ __noinline__ void run_phase(const P p) {
    constexpr int NSTRIP = 1 << NSHIFT;
    constexpr int WPAD   = NSTRIP + 4;
    constexpr int NW     = (NSHIFT >= 6) ? 4 : 2;
    constexpr int MW     = 16 / NW;
    constexpr int MFR    = 128 / (16 * MW);
    constexpr int NFR    = NSTRIP / (16 * NW);
    constexpr int ABUF   = 9216;                // 128*36 hi + 128*36 lo
    constexpr int WBUF   = 2 * 32 * WPAD;
    extern __shared__ float sm[];
    float* const Wbase = sm + 2 * ABUF;
    __shared__ int s_last;

    const int tid = threadIdx.x;
    const int wid = tid >> 5;
    const int ntiles = p.N >> NSHIFT;
    const int cta = blockIdx.x;

    if (cta < ntiles * p.kch) {
        const int tile = cta / p.kch, kc = cta - tile * p.kch;
        const int n0 = tile << NSHIFT;
        const int KL = p.Ktot / p.kch;
        const int k0 = kc * KL;
        const int niter = KL >> 5;
        const int wm = wid % MW, wn = wid / MW;

        wmma::fragment<wmma::accumulator, 16, 16, 8, float> C[MFR * NFR];
        #pragma unroll
        for (int i = 0; i < MFR * NFR; i++) wmma::fill_fragment(C[i], 0.f);

        const float* WHg = g_whi + p.woff;
        const float* WLg = g_wlo + p.woff;
        const unsigned int asmA = (unsigned int)__cvta_generic_to_shared(sm);
        const unsigned int asmW = (unsigned int)__cvta_generic_to_shared(Wbase);

        auto issueA = [&](int buf, int kg) {
            #pragma unroll
            for (int i = 0; i < 2; i++) {
                int c = tid + (i << 9);
                int row = c >> 3, kq = (c & 7) << 2;
                int k = kg + kq;
                const float *sh, *sl;
                if (k < p.K1) {
                    size_t o = (size_t)row * p.K1 + k;
                    sh = p.A1h + o; sl = p.A1l + o;
                } else {
                    size_t o = (size_t)row * Hsz + (k - p.K1);
                    sh = p.A2h + o; sl = p.A2l + o;
                }
                unsigned int d = asmA + (unsigned int)(buf * ABUF + row * 36 + kq) * 4u;
                cpa16(d, sh);
                cpa16(d + 4608u * 4u, sl);
            }
        };
        auto issueW = [&](int buf, int kg) {
            constexpr int NC4 = NSTRIP / 4;
            constexpr int CPL = 32 * NC4;
            #pragma unroll
            for (int i = 0; i < (CPL + 511) / 512; i++) {
                int c = tid + (i << 9);
                if (CPL >= 512 || c < CPL) {
                    int kk = c / NC4, nc = (c - kk * NC4) << 2;
                    size_t s = (size_t)(kg + kk) * p.N + (n0 + nc);
                    unsigned int d = asmW + (unsigned int)(buf * WBUF + kk * WPAD + nc) * 4u;
                    cpa16(d, WHg + s);
                    cpa16(d + (unsigned int)(32 * WPAD) * 4u, WLg + s);
                }
            }
        };
        auto compute = [&](int buf) {
            const float* AH = sm + buf * ABUF;
            const float* AL = AH + 4608;
            const float* WH = Wbase + buf * WBUF;
            const float* WL = WH + 32 * WPAD;
            #pragma unroll
            for (int ks = 0; ks < 4; ++ks) {
                wmma::fragment<wmma::matrix_b, 16,16,8, wmma::precision::tf32, wmma::row_major> bH[NFR], bL[NFR];
                #pragma unroll
                for (int nf = 0; nf < NFR; ++nf) {
                    int ncol = (wn * NFR + nf) * 16;
                    wmma::load_matrix_sync(bH[nf], WH + ks * 8 * WPAD + ncol, WPAD);
                    wmma::load_matrix_sync(bL[nf], WL + ks * 8 * WPAD + ncol, WPAD);
                }
                #pragma unroll
                for (int mf = 0; mf < MFR; ++mf) {
                    int mrow = (wm * MFR + mf) * 16;
                    wmma::fragment<wmma::matrix_a, 16,16,8, wmma::precision::tf32, wmma::row_major> aH, aL;
                    wmma::load_matrix_sync(aH, AH + mrow * 36 + ks * 8, 36);
                    wmma::load_matrix_sync(aL, AL + mrow * 36 + ks * 8, 36);
                    #pragma unroll
                    for (int nf = 0; nf < NFR; ++nf) {
                        wmma::mma_sync(C[mf*NFR+nf], aH, bH[nf], C[mf*NFR+nf]);
                        wmma::mma_sync(C[mf*NFR+nf], aH, bL[nf], C[mf*NFR+nf]);
                        wmma::mma_sync(C[mf*NFR+nf], aL, bH[nf], C[mf*NFR+nf]);
                    }
                }
            }
        };

        // ---- pipelined K loop ----
        issueA(0, k0); issueW(0, k0); cpa_commit();
        cpa_waitall();
        __syncthreads();
        for (int it = 0; it < niter; ++it) {
            const int cur = it & 1;
            const bool more = (it + 1 < niter);
            if (more) {
                issueA(cur ^ 1, k0 + ((it + 1) << 5));
                issueW(cur ^ 1, k0 + ((it + 1) << 5));
                cpa_commit();
            }
            compute(cur);
            cpa_waitall();
            __syncthreads();
        }

        // ---- dump C to smem out tile (128 x NSTRIP, ld=NSTRIP) ----
        #pragma unroll
        for (int mf = 0; mf < MFR; ++mf)
            #pragma unroll
            for (int nf = 0; nf < NFR; ++nf)
                wmma::store_matrix_sync(sm + ((wm * MFR + mf) * 16) * NSTRIP + (wn * NFR + nf) * 16,
                                        C[mf*NFR+nf], NSTRIP, wmma::mem_row_major);
        __syncthreads();

        // ---- split-K accumulate + fused epilogue on last CTA of tile ----
        for (int e = tid; e < 128 * NSTRIP; e += TPB) {
            int m = e >> NSHIFT, ln = e & (NSTRIP - 1);
            atomicAdd(g_acc + m * ACCW + n0 + ln, sm[e]);
        }
        __threadfence();
        __syncthreads();
        if (tid == 0) s_last = (atomicAdd(&g_cnt[tile], 1) == p.kch - 1) ? 1 : 0;
        __syncthreads();
        if (s_last) {
            if (tid == 0) g_cnt[tile] = 0;
            if (!p.lstm) {
                for (int e = tid; e < 128 * NSTRIP; e += TPB) {
                    int m = e >> NSHIFT, ln = e & (NSTRIP - 1);
                    int n = n0 + ln;
                    float* ap = g_acc + m * ACCW + n;
                    float z = __ldcg(ap) + p.b1[n];
                    __stcg(ap, 0.f);
                    float s = 2.f * sigm(z);
                    float v = s * __ldcg(p.mult + m * p.mstride + n);
                    size_t o = (size_t)m * p.ostride + n;
                    __stcg(p.out + o, v);
                    float hh = t32(v);
                    __stcg(p.outh + o, hh);
                    __stcg(p.outl + o, t32(v - hh));
                }
            } else {
                constexpr int UC = NSTRIP >> 2;
                for (int e = tid; e < 128 * UC; e += TPB) {
                    int m = e >> (NSHIFT - 2), lu = e & (UC - 1);
                    int u = (n0 >> 2) + lu;
                    float* ap = g_acc + m * ACCW + n0 + lu * 4;
                    float zi = __ldcg(ap+0) + p.b1[u]         + p.b2[u];
                    float zf = __ldcg(ap+1) + p.b1[Hsz+u]     + p.b2[Hsz+u];
                    float zg = __ldcg(ap+2) + p.b1[2*Hsz+u]   + p.b2[2*Hsz+u];
                    float zo = __ldcg(ap+3) + p.b1[3*Hsz+u]   + p.b2[3*Hsz+u];
                    __stcg(ap+0, 0.f); __stcg(ap+1, 0.f);
                    __stcg(ap+2, 0.f); __stcg(ap+3, 0.f);
                    float cn = sigm(zf) * __ldcg(p.fc + m*Hsz + u) + sigm(zi) * tanhf(zg);
                    float hn = sigm(zo) * tanhf(cn);
                    __stcg(p.fc + m*Hsz + u, cn);
                    __stcg(p.fh + m*Hsz + u, hn);
                    float hh = t32(hn);
                    __stcg(p.fhh + m*Hsz + u, hh);
                    __stcg(p.fhl + m*Hsz + u, t32(hn - hh));
                }
            }
        }
    }
    gridbar();
}

__device__ __forceinline__ P mogP(const float* Ah, const float* Al, int K, size_t woff,
                                  int N, int kch, const float* bias,
                                  const float* mult, int mstride,
                                  float* out, float* outh, float* outl, int ostride) {
    P p;
    p.A1h = Ah; p.A1l = Al; p.A2h = Ah; p.A2l = Al; p.K1 = K; p.Ktot = K;
    p.woff = woff; p.N = N; p.kch = kch; p.lstm = 0;
    p.b1 = bias; p.b2 = bias;
    p.mult = mult; p.mstride = mstride;
    p.out = out; p.outh = outh; p.outl = outl; p.ostride = ostride;
    p.fc = 0; p.fh = 0; p.fhh = 0; p.fhl = 0;
    return p;
}

__device__ __forceinline__ P lstmP(const float* A1h, const float* A1l, int K1,
                                   const float* A2h, const float* A2l, int Ktot,
                                   size_t woff, const float* bih, const float* bhh,
                                   float* fc, float* fh, float* fhh, float* fhl, int kch) {
    P p;
    p.A1h = A1h; p.A1l = A1l; p.A2h = A2h; p.A2l = A2l; p.K1 = K1; p.Ktot = Ktot;
    p.woff = woff; p.N = 4096; p.kch = kch; p.lstm = 1;
    p.b1 = bih; p.b2 = bhh;
    p.mult = 0; p.mstride = 0; p.out = 0; p.outh = 0; p.outl = 0; p.ostride = 0;
    p.fc = fc; p.fh = fh; p.fhh = fhh; p.fhl = fhl;
    return p;
}

__global__ void __launch_bounds__(TPB, 1) mog_kernel(
    const float* in_seq,
    const float* c1Qb, const float* c1Rb, const float* c1bih, const float* c1bhh,
    const float* c2Qb, const float* c2Rb, const float* c2bih, const float* c2bhh,
    const float* linW, const float* linb, float* out)
{
    for (int i = blockIdx.x*TPB + threadIdx.x; i < Bsz*Hsz; i += NB*TPB) {
        g_h1[i] = 0.f; g_c1[i] = 0.f; g_h2[i] = 0.f; g_c2[i] = 0.f;
        g_h1h[i] = 0.f; g_h1l[i] = 0.f; g_h2h[i] = 0.f; g_h2l[i] = 0.f;
    }
    gridbar();

    for (int t = 0; t < Tsz; ++t) {
        // ---- layer 1 mogrify ----
        run_phase<5>(mogP(g_h1h, g_h1l, Hsz, OQ1(0), ISZ, 32, c1Qb,
                          in_seq + t*ISZ, Tsz*ISZ, g_x, g_xh, g_xl, ISZ));
        run_phase<5>(mogP(g_xh, g_xl, ISZ, OR1(0), Hsz, 4, c1Rb,
                          g_h1, Hsz, g_hm, g_hmh, g_hml, Hsz));
        run_phase<5>(mogP(g_hmh, g_hml, Hsz, OQ1(1), ISZ, 32, c1Qb + ISZ,
                          g_x, ISZ, g_x, g_xh, g_xl, ISZ));
        run_phase<5>(mogP(g_xh, g_xl, ISZ, OR1(1), Hsz, 4, c1Rb + Hsz,
                          g_hm, Hsz, g_hm, g_hmh, g_hml, Hsz));
        run_phase<5>(mogP(g_hmh, g_hml, Hsz, OQ1(2), ISZ, 32, c1Qb + 2*ISZ,
                          g_x, ISZ, g_x, g_xh, g_xl, ISZ));
        // ---- layer 1 LSTM ----  N=4096: 32 tiles x kch4 (KL=288)
        run_phase<7>(lstmP(g_xh, g_xl, ISZ, g_hmh, g_hml, ISZ + Hsz, OL1,
                           c1bih, c1bhh, g_c1, g_h1, g_h1h, g_h1l, 4));
        // ---- layer 2 mogrify ----  N=1024: 8 tiles x kch16 (KL=64)
        run_phase<7>(mogP(g_h2h, g_h2l, Hsz, OQ2(0), Hsz, 16, c2Qb,
                          g_h1, Hsz, g_x2, g_x2h, g_x2l, Hsz));
        run_phase<7>(mogP(g_x2h, g_x2l, Hsz, OR2(0), Hsz, 16, c2Rb,
                          g_h2, Hsz, g_hm, g_hmh, g_hml, Hsz));
        run_phase<7>(mogP(g_hmh, g_hml, Hsz, OQ2(1), Hsz, 16, c2Qb + Hsz,
                          g_x2, Hsz, g_x2, g_x2h, g_x2l, Hsz));
        run_phase<7>(mogP(g_x2h, g_x2l, Hsz, OR2(1), Hsz, 16, c2Rb + Hsz,
                          g_hm, Hsz, g_hm, g_hmh, g_hml, Hsz));
        run_phase<7>(mogP(g_hmh, g_hml, Hsz, OQ2(2), Hsz, 16, c2Qb + 2*Hsz,
                          g_x2, Hsz, g_x2, g_x2h, g_x2l, Hsz));
        // ---- layer 2 LSTM ----  N=4096: 32 tiles x kch4 (KL=512)
        run_phase<7>(lstmP(g_x2h, g_x2l, Hsz, g_hmh, g_hml, 2*Hsz, OL2,
                           c2bih, c2bhh, g_c2, g_h2, g_h2h, g_h2l, 4));
    }

    // final linear
    if (blockIdx.x == 0 && threadIdx.x < 256) {
        int tid = threadIdx.x;
        int b = tid >> 1, half = tid & 1;
        const float* hrow = g_h2 + b*Hsz + half*512;
        const float* w    = linW + half*512;
        float s = 0.f;
        for (int j = 0; j < 512; ++j) s += __ldcg(hrow + j) * w[j];
        s += __shfl_xor_sync(0xffffffffu, s, 1);
        if (half == 0) out[b] = s + linb[0];
    }
}

extern "C" void kernel_launch(void* const* d_in, const int* in_sizes, int n_in,
                              void* d_out, int out_size) {
    (void)in_sizes; (void)n_in; (void)out_size;
    cudaFuncSetAttribute(mog_kernel, cudaFuncAttributeMaxDynamicSharedMemorySize,
                         SMEM_BYTES);
    const float* in_seq = (const float*)d_in[0];
    const float* c1Q    = (const float*)d_in[1];
    const float* c1Qb   = (const float*)d_in[2];
    const float* c1R    = (const float*)d_in[3];
    const float* c1Rb   = (const float*)d_in[4];
    const float* c1Wih  = (const float*)d_in[5];
    const float* c1Whh  = (const float*)d_in[6];
    const float* c1bih  = (const float*)d_in[7];
    const float* c1bhh  = (const float*)d_in[8];
    const float* c2Q    = (const float*)d_in[9];
    const float* c2Qb   = (const float*)d_in[10];
    const float* c2R    = (const float*)d_in[11];
    const float* c2Rb   = (const float*)d_in[12];
    const float* c2Wih  = (const float*)d_in[13];
    const float* c2Whh  = (const float*)d_in[14];
    const float* c2bih  = (const float*)d_in[15];
    const float* c2bhh  = (const float*)d_in[16];
    const float* linW   = (const float*)d_in[17];
    const float* linb   = (const float*)d_in[18];

    preconv_kernel<<<dim3(256, 12), 256>>>(c1Q, c1R, c1Wih, c1Whh,
                                           c2Q, c2R, c2Wih, c2Whh);
    mog_kernel<<<NB, TPB, SMEM_BYTES>>>(in_seq,
                                        c1Qb, c1Rb, c1bih, c1bhh,
                                        c2Qb, c2Rb, c2bih, c2bhh,
                                        linW, linb, (float*)d_out);
}

// round 8
// speedup vs baseline: 1.5704x; 1.5704x over previous
#include <cuda_runtime.h>
#include <cuda_bf16.h>
#include <mma.h>
#include <math.h>
#include <cstdint>

using namespace nvcuda;
typedef __nv_bfloat16 bf16;

#define NB   128
#define TPB  512
#define Bsz  128
#define Tsz  512
#define ISZ  128
#define Hsz  1024
#define ACCW 4096
#define SMEM_BYTES 59392

// ---- preconverted weight planes: [k][n] per phase, bf16 hi/lo ----------------
#define WTOT 19005440
__device__ bf16 g_wh[WTOT];
__device__ bf16 g_wl[WTOT];
#define OQ1(i) ((size_t)(i)*131072)
#define OR1(i) (393216 + (size_t)(i)*131072)
#define OL1    655360
#define OQ2(i) (5373952 + (size_t)(i)*1048576)
#define OR2(i) (8519680 + (size_t)(i)*1048576)
#define OL2    10616832

// ---------------- persistent state --------------------------------------------
__device__ float g_h1 [Bsz*Hsz];
__device__ float g_c1 [Bsz*Hsz];
__device__ float g_h2 [Bsz*Hsz];
__device__ float g_c2 [Bsz*Hsz];
__device__ float g_x  [Bsz*ISZ];
__device__ float g_x2 [Bsz*Hsz];
__device__ float g_hm [Bsz*Hsz];
__device__ bf16  g_h1h[Bsz*Hsz], g_h1l[Bsz*Hsz];
__device__ bf16  g_h2h[Bsz*Hsz], g_h2l[Bsz*Hsz];
__device__ bf16  g_xh [Bsz*ISZ], g_xl [Bsz*ISZ];
__device__ bf16  g_x2h[Bsz*Hsz], g_x2l[Bsz*Hsz];
__device__ bf16  g_hmh[Bsz*Hsz], g_hml[Bsz*Hsz];
__device__ float g_acc[Bsz*ACCW];
__device__ int   g_cnt[64];
__device__ unsigned g_barcnt;
__device__ volatile unsigned g_bargen;

__device__ __forceinline__ float sigm(float z) { return 1.f / (1.f + expf(-z)); }

__device__ __forceinline__ void cpa16(unsigned int dst, const void* src) {
    asm volatile("cp.async.cg.shared.global [%0], [%1], 16;\n" :: "r"(dst), "l"(src));
}
__device__ __forceinline__ void cpa_commit() { asm volatile("cp.async.commit_group;\n"); }
__device__ __forceinline__ void cpa_waitall() { asm volatile("cp.async.wait_all;\n"); }

// ---------------- grid barrier (hot spin) --------------------------------------
__device__ __forceinline__ void gridbar() {
    __syncthreads();
    if (threadIdx.x == 0) {
        __threadfence();
        unsigned gen = g_bargen;
        if (atomicAdd(&g_barcnt, 1u) == (unsigned)(gridDim.x - 1)) {
            g_barcnt = 0;
            __threadfence();
            atomicExch((unsigned*)&g_bargen, gen + 1u);
        } else {
            while (g_bargen == gen) {}
        }
        __threadfence();
    }
    __syncthreads();
}

// ---------------- weight preconversion (once per launch) -----------------------
__global__ void preconv_kernel(
    const float* c1Q, const float* c1R, const float* c1Wih, const float* c1Whh,
    const float* c2Q, const float* c2R, const float* c2Wih, const float* c2Whh)
{
    int seg = blockIdx.y;
    const float *src = 0, *src2 = 0;
    int K = 0, N = 0, LD = 0, K1 = 0, lstm = 0;
    size_t dst = 0;
    switch (seg) {
        case 0: case 1: case 2:
            src = c1Q + (size_t)seg*131072; K = 1024; N = 128; LD = 1024; dst = OQ1(seg); break;
        case 3: case 4:
            src = c1R + (size_t)(seg-3)*131072; K = 128; N = 1024; LD = 128; dst = OR1(seg-3); break;
        case 5:
            src = c1Wih; src2 = c1Whh; K = 1152; N = 4096; K1 = 128; lstm = 1; dst = OL1; break;
        case 6: case 7: case 8:
            src = c2Q + (size_t)(seg-6)*1048576; K = 1024; N = 1024; LD = 1024; dst = OQ2(seg-6); break;
        case 9: case 10:
            src = c2R + (size_t)(seg-9)*1048576; K = 1024; N = 1024; LD = 1024; dst = OR2(seg-9); break;
        default:
            src = c2Wih; src2 = c2Whh; K = 2048; N = 4096; K1 = 1024; lstm = 1; dst = OL2; break;
    }
    size_t tot = (size_t)K * N;
    for (size_t i = (size_t)blockIdx.x*blockDim.x + threadIdx.x; i < tot;
         i += (size_t)gridDim.x*blockDim.x) {
        int k = (int)(i / N), n = (int)(i % N);
        float v;
        if (!lstm) {
            v = src[(size_t)n*LD + k];
        } else {
            int g = n & 3, u = n >> 2;
            int row = g*Hsz + u;
            v = (k < K1) ? src[(size_t)row*K1 + k] : src2[(size_t)row*Hsz + (k - K1)];
        }
        bf16 h = __float2bfloat16(v);
        g_wh[dst + i] = h;
        g_wl[dst + i] = __float2bfloat16(v - __bfloat162float(h));
    }
}

// ---------------- phase descriptor ---------------------------------------------
struct P {
    const bf16 *A1h, *A1l, *A2h, *A2l; int K1, Ktot;
    size_t woff;
    int N, kch, lstm;
    const float *b1, *b2;
    const float *mult; int mstride;
    float *out; bf16 *outh, *outl; int ostride;
    float *fc, *fh; bf16 *fhh, *fhl;
};

// one GEMM phase: 128 x NSTRIP per CTA, split-K, 32-k macro-tiles, cp.async of
// pre-split bf16 hi/lo planes, 4-term bf16 wmma (full fp32-equivalent product).
template<int NSHIFT>
__device__ __noinline__ void run_phase(const P p) {
    constexpr int NSTRIP = 1 << NSHIFT;
    constexpr int WPITCH = NSTRIP + 8;
    constexpr int NW     = (NSHIFT >= 6) ? 4 : 2;
    constexpr int MW     = 16 / NW;
    constexpr int MFR    = 8 / MW;
    constexpr int NFR    = NSTRIP / (16 * NW);
    constexpr int AP     = 40;                 // A pitch (bf16 elems)
    constexpr int ABUFE  = 2 * 128 * AP;       // hi+lo elems per A buffer
    constexpr int WBUFE  = 2 * 32 * WPITCH;
    extern __shared__ float smf[];
    bf16* const sb = (bf16*)smf;
    bf16* const Wb = sb + 2 * ABUFE;
    __shared__ int s_last;

    const int tid = threadIdx.x;
    const int wid = tid >> 5;
    const int ntiles = p.N >> NSHIFT;
    const int cta = blockIdx.x;

    if (cta < ntiles * p.kch) {
        const int tile = cta / p.kch, kc = cta - tile * p.kch;
        const int n0 = tile << NSHIFT;
        const int KL = p.Ktot / p.kch;
        const int k0 = kc * KL;
        const int niter = KL >> 5;
        const int wm = wid % MW, wn = wid / MW;

        wmma::fragment<wmma::accumulator, 16, 16, 16, float> C[MFR * NFR];
        #pragma unroll
        for (int i = 0; i < MFR * NFR; i++) wmma::fill_fragment(C[i], 0.f);

        const bf16* WHg = g_wh + p.woff;
        const bf16* WLg = g_wl + p.woff;
        const unsigned int asmA = (unsigned int)__cvta_generic_to_shared(sb);
        const unsigned int asmW = (unsigned int)__cvta_generic_to_shared(Wb);

        auto issueA = [&](int buf, int kg) {
            #pragma unroll
            for (int i = 0; i < 2; i++) {
                int o = tid + (i << 9);            // 1024 chunk ops
                int pl = o >> 9;
                int r = (o & 511) >> 2, c = o & 3;
                int k = kg + (c << 3);
                const bf16* src;
                if (k < p.K1) src = (pl ? p.A1l : p.A1h) + (size_t)r * p.K1 + k;
                else          src = (pl ? p.A2l : p.A2h) + (size_t)r * Hsz + (k - p.K1);
                unsigned int d = asmA +
                    (unsigned int)(buf * ABUFE + pl * 128 * AP + r * AP + (c << 3)) * 2u;
                cpa16(d, src);
            }
        };
        auto issueW = [&](int buf, int kg) {
            constexpr int CPR = NSTRIP / 8;        // 16B chunks per row
            constexpr int TOT = 32 * CPR * 2;
            if (tid < TOT) {
                int pl = tid / (32 * CPR);
                int rem = tid - pl * 32 * CPR;
                int kk = rem / CPR, c = rem - kk * CPR;
                size_t s = (size_t)(kg + kk) * p.N + n0 + (c << 3);
                const bf16* src = (pl ? WLg : WHg) + s;
                unsigned int d = asmW +
                    (unsigned int)(buf * WBUFE + pl * 32 * WPITCH + kk * WPITCH + (c << 3)) * 2u;
                cpa16(d, src);
            }
        };
        auto compute = [&](int buf) {
            const bf16* AH = sb + buf * ABUFE;
            const bf16* AL = AH + 128 * AP;
            const bf16* WH = Wb + buf * WBUFE;
            const bf16* WL = WH + 32 * WPITCH;
            #pragma unroll
            for (int ks = 0; ks < 2; ++ks) {
                wmma::fragment<wmma::matrix_b, 16,16,16, bf16, wmma::row_major> bH[NFR], bL[NFR];
                #pragma unroll
                for (int nf = 0; nf < NFR; ++nf) {
                    int ncol = (wn * NFR + nf) * 16;
                    wmma::load_matrix_sync(bH[nf], WH + ks * 16 * WPITCH + ncol, WPITCH);
                    wmma::load_matrix_sync(bL[nf], WL + ks * 16 * WPITCH + ncol, WPITCH);
                }
                #pragma unroll
                for (int mf = 0; mf < MFR; ++mf) {
                    int mrow = (wm * MFR + mf) * 16;
                    wmma::fragment<wmma::matrix_a, 16,16,16, bf16, wmma::row_major> aH, aL;
                    wmma::load_matrix_sync(aH, AH + mrow * AP + ks * 16, AP);
                    wmma::load_matrix_sync(aL, AL + mrow * AP + ks * 16, AP);
                    #pragma unroll
                    for (int nf = 0; nf < NFR; ++nf) {
                        wmma::mma_sync(C[mf*NFR+nf], aH, bH[nf], C[mf*NFR+nf]);
                        wmma::mma_sync(C[mf*NFR+nf], aH, bL[nf], C[mf*NFR+nf]);
                        wmma::mma_sync(C[mf*NFR+nf], aL, bH[nf], C[mf*NFR+nf]);
                        wmma::mma_sync(C[mf*NFR+nf], aL, bL[nf], C[mf*NFR+nf]);
                    }
                }
            }
        };

        // ---- pipelined K loop ----
        issueA(0, k0); issueW(0, k0); cpa_commit();
        cpa_waitall();
        __syncthreads();
        for (int it = 0; it < niter; ++it) {
            const int cur = it & 1;
            const bool more = (it + 1 < niter);
            if (more) {
                issueA(cur ^ 1, k0 + ((it + 1) << 5));
                issueW(cur ^ 1, k0 + ((it + 1) << 5));
                cpa_commit();
            }
            compute(cur);
            cpa_waitall();
            __syncthreads();
        }

        // ---- dump C to smem out tile (128 x NSTRIP floats) ----
        #pragma unroll
        for (int mf = 0; mf < MFR; ++mf)
            #pragma unroll
            for (int nf = 0; nf < NFR; ++nf)
                wmma::store_matrix_sync(smf + ((wm * MFR + mf) * 16) * NSTRIP + (wn * NFR + nf) * 16,
                                        C[mf*NFR+nf], NSTRIP, wmma::mem_row_major);
        __syncthreads();

        // ---- split-K accumulate + fused epilogue on last CTA of tile ----
        for (int e = tid; e < 128 * NSTRIP; e += TPB) {
            int m = e >> NSHIFT, ln = e & (NSTRIP - 1);
            atomicAdd(g_acc + m * ACCW + n0 + ln, smf[e]);
        }
        __threadfence();
        __syncthreads();
        if (tid == 0) s_last = (atomicAdd(&g_cnt[tile], 1) == p.kch - 1) ? 1 : 0;
        __syncthreads();
        if (s_last) {
            if (tid == 0) g_cnt[tile] = 0;
            if (!p.lstm) {
                for (int e = tid; e < 128 * NSTRIP; e += TPB) {
                    int m = e >> NSHIFT, ln = e & (NSTRIP - 1);
                    int n = n0 + ln;
                    float* ap = g_acc + m * ACCW + n;
                    float z = __ldcg(ap) + p.b1[n];
                    __stcg(ap, 0.f);
                    float s = 2.f * sigm(z);
                    float v = s * __ldcg(p.mult + m * p.mstride + n);
                    size_t o = (size_t)m * p.ostride + n;
                    __stcg(p.out + o, v);
                    bf16 bh = __float2bfloat16(v);
                    __stcg((unsigned short*)p.outh + o, __bfloat16_as_ushort(bh));
                    __stcg((unsigned short*)p.outl + o,
                           __bfloat16_as_ushort(__float2bfloat16(v - __bfloat162float(bh))));
                }
            } else {
                constexpr int UC = NSTRIP >> 2;
                for (int e = tid; e < 128 * UC; e += TPB) {
                    int m = e >> (NSHIFT - 2), lu = e & (UC - 1);
                    int u = (n0 >> 2) + lu;
                    float* ap = g_acc + m * ACCW + n0 + lu * 4;
                    float zi = __ldcg(ap+0) + p.b1[u]         + p.b2[u];
                    float zf = __ldcg(ap+1) + p.b1[Hsz+u]     + p.b2[Hsz+u];
                    float zg = __ldcg(ap+2) + p.b1[2*Hsz+u]   + p.b2[2*Hsz+u];
                    float zo = __ldcg(ap+3) + p.b1[3*Hsz+u]   + p.b2[3*Hsz+u];
                    __stcg(ap+0, 0.f); __stcg(ap+1, 0.f);
                    __stcg(ap+2, 0.f); __stcg(ap+3, 0.f);
                    float cn = sigm(zf) * __ldcg(p.fc + m*Hsz + u) + sigm(zi) * tanhf(zg);
                    float hn = sigm(zo) * tanhf(cn);
                    __stcg(p.fc + m*Hsz + u, cn);
                    __stcg(p.fh + m*Hsz + u, hn);
                    bf16 bh = __float2bfloat16(hn);
                    __stcg((unsigned short*)p.fhh + m*Hsz + u, __bfloat16_as_ushort(bh));
                    __stcg((unsigned short*)p.fhl + m*Hsz + u,
                           __bfloat16_as_ushort(__float2bfloat16(hn - __bfloat162float(bh))));
                }
            }
        }
    }
    gridbar();
}

__device__ __forceinline__ P mogP(const bf16* Ah, const bf16* Al, int K, size_t woff,
                                  int N, int kch, const float* bias,
                                  const float* mult, int mstride,
                                  float* out, bf16* outh, bf16* outl, int ostride) {
    P p;
    p.A1h = Ah; p.A1l = Al; p.A2h = Ah; p.A2l = Al; p.K1 = K; p.Ktot = K;
    p.woff = woff; p.N = N; p.kch = kch; p.lstm = 0;
    p.b1 = bias; p.b2 = bias;
    p.mult = mult; p.mstride = mstride;
    p.out = out; p.outh = outh; p.outl = outl; p.ostride = ostride;
    p.fc = 0; p.fh = 0; p.fhh = 0; p.fhl = 0;
    return p;
}

__device__ __forceinline__ P lstmP(const bf16* A1h, const bf16* A1l, int K1,
                                   const bf16* A2h, const bf16* A2l, int Ktot,
                                   size_t woff, const float* bih, const float* bhh,
                                   float* fc, float* fh, bf16* fhh, bf16* fhl, int kch) {
    P p;
    p.A1h = A1h; p.A1l = A1l; p.A2h = A2h; p.A2l = A2l; p.K1 = K1; p.Ktot = Ktot;
    p.woff = woff; p.N = 4096; p.kch = kch; p.lstm = 1;
    p.b1 = bih; p.b2 = bhh;
    p.mult = 0; p.mstride = 0; p.out = 0; p.outh = 0; p.outl = 0; p.ostride = 0;
    p.fc = fc; p.fh = fh; p.fhh = fhh; p.fhl = fhl;
    return p;
}

__global__ void __launch_bounds__(TPB, 1) mog_kernel(
    const float* in_seq,
    const float* c1Qb, const float* c1Rb, const float* c1bih, const float* c1bhh,
    const float* c2Qb, const float* c2Rb, const float* c2bih, const float* c2bhh,
    const float* linW, const float* linb, float* out)
{
    for (int i = blockIdx.x*TPB + threadIdx.x; i < Bsz*Hsz; i += NB*TPB) {
        g_h1[i] = 0.f; g_c1[i] = 0.f; g_h2[i] = 0.f; g_c2[i] = 0.f;
        unsigned short z = 0;
        ((unsigned short*)g_h1h)[i] = z; ((unsigned short*)g_h1l)[i] = z;
        ((unsigned short*)g_h2h)[i] = z; ((unsigned short*)g_h2l)[i] = z;
    }
    gridbar();

    for (int t = 0; t < Tsz; ++t) {
        // ---- layer 1 mogrify ----
        run_phase<5>(mogP(g_h1h, g_h1l, Hsz, OQ1(0), ISZ, 32, c1Qb,
                          in_seq + t*ISZ, Tsz*ISZ, g_x, g_xh, g_xl, ISZ));
        run_phase<5>(mogP(g_xh, g_xl, ISZ, OR1(0), Hsz, 4, c1Rb,
                          g_h1, Hsz, g_hm, g_hmh, g_hml, Hsz));
        run_phase<5>(mogP(g_hmh, g_hml, Hsz, OQ1(1), ISZ, 32, c1Qb + ISZ,
                          g_x, ISZ, g_x, g_xh, g_xl, ISZ));
        run_phase<5>(mogP(g_xh, g_xl, ISZ, OR1(1), Hsz, 4, c1Rb + Hsz,
                          g_hm, Hsz, g_hm, g_hmh, g_hml, Hsz));
        run_phase<5>(mogP(g_hmh, g_hml, Hsz, OQ1(2), ISZ, 32, c1Qb + 2*ISZ,
                          g_x, ISZ, g_x, g_xh, g_xl, ISZ));
        // ---- layer 1 LSTM ----  N=4096: 64 tiles x kch2 (KL=576, niter 18)
        run_phase<6>(lstmP(g_xh, g_xl, ISZ, g_hmh, g_hml, ISZ + Hsz, OL1,
                           c1bih, c1bhh, g_c1, g_h1, g_h1h, g_h1l, 2));
        // ---- layer 2 mogrify ----  N=1024: 16 tiles x kch8 (KL=128, niter 4)
        run_phase<6>(mogP(g_h2h, g_h2l, Hsz, OQ2(0), Hsz, 8, c2Qb,
                          g_h1, Hsz, g_x2, g_x2h, g_x2l, Hsz));
        run_phase<6>(mogP(g_x2h, g_x2l, Hsz, OR2(0), Hsz, 8, c2Rb,
                          g_h2, Hsz, g_hm, g_hmh, g_hml, Hsz));
        run_phase<6>(mogP(g_hmh, g_hml, Hsz, OQ2(1), Hsz, 8, c2Qb + Hsz,
                          g_x2, Hsz, g_x2, g_x2h, g_x2l, Hsz));
        run_phase<6>(mogP(g_x2h, g_x2l, Hsz, OR2(1), Hsz, 8, c2Rb + Hsz,
                          g_hm, Hsz, g_hm, g_hmh, g_hml, Hsz));
        run_phase<6>(mogP(g_hmh, g_hml, Hsz, OQ2(2), Hsz, 8, c2Qb + 2*Hsz,
                          g_x2, Hsz, g_x2, g_x2h, g_x2l, Hsz));
        // ---- layer 2 LSTM ----  N=4096: 64 tiles x kch2 (KL=1024, niter 32)
        run_phase<6>(lstmP(g_x2h, g_x2l, Hsz, g_hmh, g_hml, 2*Hsz, OL2,
                           c2bih, c2bhh, g_c2, g_h2, g_h2h, g_h2l, 2));
    }

    // final linear
    if (blockIdx.x == 0 && threadIdx.x < 256) {
        int tid = threadIdx.x;
        int b = tid >> 1, half = tid & 1;
        const float* hrow = g_h2 + b*Hsz + half*512;
        const float* w    = linW + half*512;
        float s = 0.f;
        for (int j = 0; j < 512; ++j) s += __ldcg(hrow + j) * w[j];
        s += __shfl_xor_sync(0xffffffffu, s, 1);
        if (half == 0) out[b] = s + linb[0];
    }
}

extern "C" void kernel_launch(void* const* d_in, const int* in_sizes, int n_in,
                              void* d_out, int out_size) {
    (void)in_sizes; (void)n_in; (void)out_size;
    cudaFuncSetAttribute(mog_kernel, cudaFuncAttributeMaxDynamicSharedMemorySize,
                         SMEM_BYTES);
    const float* in_seq = (const float*)d_in[0];
    const float* c1Q    = (const float*)d_in[1];
    const float* c1Qb   = (const float*)d_in[2];
    const float* c1R    = (const float*)d_in[3];
    const float* c1Rb   = (const float*)d_in[4];
    const float* c1Wih  = (const float*)d_in[5];
    const float* c1Whh  = (const float*)d_in[6];
    const float* c1bih  = (const float*)d_in[7];
    const float* c1bhh  = (const float*)d_in[8];
    const float* c2Q    = (const float*)d_in[9];
    const float* c2Qb   = (const float*)d_in[10];
    const float* c2R    = (const float*)d_in[11];
    const float* c2Rb   = (const float*)d_in[12];
    const float* c2Wih  = (const float*)d_in[13];
    const float* c2Whh  = (const float*)d_in[14];
    const float* c2bih  = (const float*)d_in[15];
    const float* c2bhh  = (const float*)d_in[16];
    const float* linW   = (const float*)d_in[17];
    const float* linb   = (const float*)d_in[18];

    preconv_kernel<<<dim3(256, 12), 256>>>(c1Q, c1R, c1Wih, c1Whh,
                                           c2Q, c2R, c2Wih, c2Whh);
    mog_kernel<<<NB, TPB, SMEM_BYTES>>>(in_seq,
                                        c1Qb, c1Rb, c1bih, c1bhh,
                                        c2Qb, c2Rb, c2bih, c2bhh,
                                        linW, linb, (float*)d_out);
}